// round 6
// baseline (speedup 1.0000x reference)
#include <cuda_runtime.h>

// Problem constants (shapes fixed by the dataset)
#define B 16
#define F 256
#define T 8192
#define KKEEP 204                 // k = int(256 * (1 - 0.2))

#define N1 (B * F * T)            // 33,554,432 floats per output tensor
#define N4_MASKED (N1 / 4)        // 8,388,608 float4 (masked_x half)

// Block partition (single kernel) — HEAVY blocks scheduled FIRST:
//   broadcast region: 1024 blocks x 8192 float4 (128 KB write-only each)
//   masked region:    8192 blocks x 1024 float4 (32 KB r+w each)
#define BCAST_BLOCKS 1024
#define BB_F4 8192
#define MASKED_BLOCKS 8192
#define MB_F4 1024

// kept(f) <=> #{j : x2[j] > x2[f]} < KKEEP   (tie-correct vs top_k kth value)
// binary  = kept && (x2 > 0)                 (probs > 0.5 <=> wta > 0)
__global__ void fused_kernel(const float* __restrict__ w_mask,
                             const float* __restrict__ noise,
                             const float4* __restrict__ x,
                             float4* __restrict__ out) {
    // mask_s is read as float4 -> must be 16B aligned (LDS.128 alignment trap)
    __shared__ __align__(16) float s[F];
    __shared__ __align__(16) float mask_s[F];
    __shared__ int cnt[8];

    const int tid = threadIdx.x;                    // 256 threads

    if (blockIdx.x < BCAST_BLOCKS) {
        // ---- binary_mask block (heavy, write-only): FULL mask row ----
        const int w0 = blockIdx.x * BB_F4;
        const int b  = w0 >> 19;                    // T*F/4 f4 per batch
        const int baseV = N4_MASKED + w0;

        const float w  = w_mask[tid];
        const float sg = 1.0f / (1.0f + __expf(-w));
        const float x2 = sg + 0.05f * noise[b * F + tid];
        s[tid] = x2;
        __syncthreads();
        int gt = 0;
#pragma unroll 16
        for (int j = 0; j < F; ++j)
            gt += (s[j] > x2) ? 1 : 0;              // uniform-addr LDS: N=1
        mask_s[tid] = (gt < KKEEP && x2 > 0.0f) ? 1.0f : 0.0f;
        __syncthreads();

        // f4 lane = (w0 + it*256 + tid) & 63 = tid & 63
        const float4 m4 = ((const float4*)mask_s)[tid & 63];
#pragma unroll 8
        for (int it = 0; it < 32; ++it)
            __stcs(&out[baseV + it * 256 + tid], m4);
    } else {
        // ---- masked_x fine block: needs exactly ONE mask value ----
        const int idx = blockIdx.x - BCAST_BLOCKS;
        const int baseV = idx * MB_F4;              // first float4 index
        const int b  = baseV >> 19;                 // F*T/4 f4 per batch
        const int f0 = (baseV >> 11) & (F - 1);     // the block's feature row

        // Stream loads first: DRAM traffic starts before the mask math.
        float4 xv[4];
#pragma unroll
        for (int k = 0; k < 4; ++k)
            xv[k] = __ldcs(&x[baseV + k * 256 + tid]);

        // per-thread x2, then ballot-count against x2[f0]; 2 barriers total
        const float w  = w_mask[tid];
        const float sg = 1.0f / (1.0f + __expf(-w));
        const float x2 = sg + 0.05f * noise[b * F + tid];
        s[tid] = x2;
        __syncthreads();
        const float x2f = s[f0];
        const unsigned bal = __ballot_sync(0xffffffffu, x2 > x2f);
        if ((tid & 31) == 0) cnt[tid >> 5] = __popc(bal);
        __syncthreads();
        int g = 0;
#pragma unroll
        for (int i = 0; i < 8; ++i) g += cnt[i];    // every thread sums (no 3rd bar)
        const float m = (g < KKEEP && x2f > 0.0f) ? 1.0f : 0.0f;

#pragma unroll
        for (int k = 0; k < 4; ++k) {
            xv[k].x *= m; xv[k].y *= m; xv[k].z *= m; xv[k].w *= m;
            __stcs(&out[baseV + k * 256 + tid], xv[k]);
        }
    }
}

extern "C" void kernel_launch(void* const* d_in, const int* in_sizes, int n_in,
                              void* d_out, int out_size) {
    const float* x      = (const float*)d_in[0];   // (16,1,256,8192) f32
    const float* w_mask = (const float*)d_in[1];   // (1,1,1,256)     f32
    const float* noise  = (const float*)d_in[2];   // (16,1,1,256)    f32
    float* out = (float*)d_out;

    const bool has_bcast = ((long long)out_size >= 2LL * N1);
    const int blocks = (has_bcast ? BCAST_BLOCKS : 0) + MASKED_BLOCKS;

    if (has_bcast) {
        fused_kernel<<<blocks, 256>>>(w_mask, noise,
                                      (const float4*)x, (float4*)out);
    } else {
        // masked_x only: shift indexing by launching without bcast region is
        // not possible with this block mapping, so launch full grid minus
        // bcast via the same kernel semantics (bcast blocks skipped).
        fused_kernel<<<BCAST_BLOCKS + MASKED_BLOCKS, 256>>>(
            w_mask, noise, (const float4*)x, (float4*)out);
    }
}

// round 7
// speedup vs baseline: 1.0338x; 1.0338x over previous
#include <cuda_runtime.h>

// Problem constants (shapes fixed by the dataset)
#define B 16
#define F 256
#define T 8192
#define KKEEP 204                 // k = int(256 * (1 - 0.2))

#define N1 (B * F * T)            // 33,554,432 floats per output tensor
#define N4_MASKED (N1 / 4)        // 8,388,608 float4 (masked_x half)

// Interleaved partition (one kernel, 4:1 masked:bcast by blockIdx):
//   masked: 8192 blocks x 1024 f4 (one half (b,f) row; single mask value)
//   bcast:  2048 blocks x 4096 f4 (write-only; full mask row prologue)
#define MASKED_BLOCKS 8192
#define MB_F4 1024
#define BCAST_BLOCKS 2048
#define BB_F4 4096
#define GRID_TOTAL (MASKED_BLOCKS + BCAST_BLOCKS)   // 10240

// kept(f) <=> #{j : x2[j] > x2[f]} < KKEEP   (tie-correct vs top_k kth value)
// binary  = kept && (x2 > 0)                 (probs > 0.5 <=> wta > 0)
__global__ void fused_kernel(const float* __restrict__ w_mask,
                             const float* __restrict__ noise,
                             const float4* __restrict__ x,
                             float4* __restrict__ out,
                             int has_bcast) {
    __shared__ __align__(16) float s[F];
    __shared__ __align__(16) float mask_s[F];   // float4 reads -> 16B aligned
    __shared__ int cnt[8];

    const int tid = threadIdx.x;                    // 256 threads
    const int grp = blockIdx.x / 5;
    const int rem = blockIdx.x - grp * 5;

    if (rem < 4) {
        // ---- masked_x fine block: ONE mask value; skip reads if zero ----
        const int midx  = grp * 4 + rem;            // 0..8191
        const int baseV = midx * MB_F4;
        const int b  = baseV >> 19;                 // F*T/4 f4 per batch
        const int f0 = (baseV >> 11) & (F - 1);

        const float w  = w_mask[tid];
        const float sg = 1.0f / (1.0f + __expf(-w));
        const float x2 = sg + 0.05f * noise[b * F + tid];
        s[tid] = x2;
        __syncthreads();
        const float x2f = s[f0];
        const unsigned bal = __ballot_sync(0xffffffffu, x2 > x2f);
        if ((tid & 31) == 0) cnt[tid >> 5] = __popc(bal);
        __syncthreads();
        int g = 0;
#pragma unroll
        for (int i = 0; i < 8; ++i) g += cnt[i];
        const float m = (g < KKEEP && x2f > 0.0f) ? 1.0f : 0.0f;

        if (m != 0.0f) {
            float4 xv[4];
#pragma unroll
            for (int k = 0; k < 4; ++k)             // front-batched (MLP=4)
                xv[k] = __ldcs(&x[baseV + k * 256 + tid]);
#pragma unroll
            for (int k = 0; k < 4; ++k)
                __stcs(&out[baseV + k * 256 + tid], xv[k]);
        } else {
            const float4 z = make_float4(0.f, 0.f, 0.f, 0.f);
#pragma unroll
            for (int k = 0; k < 4; ++k)             // no x reads at all
                __stcs(&out[baseV + k * 256 + tid], z);
        }
    } else {
        // ---- binary_mask block (write-only): FULL mask row prologue ----
        if (!has_bcast) return;                     // output holds masked_x only
        const int w0 = grp * BB_F4;                 // 0..(2048*4096)
        const int b  = w0 >> 19;                    // T*F/4 f4 per batch
        const int baseV = N4_MASKED + w0;

        const float w  = w_mask[tid];
        const float sg = 1.0f / (1.0f + __expf(-w));
        const float x2 = sg + 0.05f * noise[b * F + tid];
        s[tid] = x2;
        __syncthreads();
        int gt = 0;
#pragma unroll 16
        for (int j = 0; j < F; ++j)
            gt += (s[j] > x2) ? 1 : 0;              // uniform-addr LDS: N=1
        mask_s[tid] = (gt < KKEEP && x2 > 0.0f) ? 1.0f : 0.0f;
        __syncthreads();

        // f4 lane = (w0 + it*256 + tid) & 63 = tid & 63  (w0, 256 ≡ 0 mod 64)
        const float4 m4 = ((const float4*)mask_s)[tid & 63];
#pragma unroll 8
        for (int it = 0; it < 16; ++it)
            __stcs(&out[baseV + it * 256 + tid], m4);
    }
}

extern "C" void kernel_launch(void* const* d_in, const int* in_sizes, int n_in,
                              void* d_out, int out_size) {
    const float* x      = (const float*)d_in[0];   // (16,1,256,8192) f32
    const float* w_mask = (const float*)d_in[1];   // (1,1,1,256)     f32
    const float* noise  = (const float*)d_in[2];   // (16,1,1,256)    f32
    float* out = (float*)d_out;

    const int has_bcast = ((long long)out_size >= 2LL * N1) ? 1 : 0;

    fused_kernel<<<GRID_TOTAL, 256>>>(w_mask, noise,
                                      (const float4*)x, (float4*)out,
                                      has_bcast);
}

// round 8
// speedup vs baseline: 1.0962x; 1.0604x over previous
#include <cuda_runtime.h>

// Problem constants (shapes fixed by the dataset)
#define B 16
#define F 256
#define T 8192
#define KKEEP 204                 // k = int(256 * (1 - 0.2))

#define N1 (B * F * T)            // 33,554,432 floats per output tensor
#define N4_MASKED (N1 / 4)        // 8,388,608 float4 (masked_x half)

// Streamer geometry (R2-proven): 256 threads, ILP 4 -> 1024 f4 per block.
#define BLK_F4 1024
#define MASKED_BLOCKS 8192        // 8192 * 1024 f4 = N4_MASKED
#define BCAST_BLOCKS 8192
#define GRID_TOTAL (MASKED_BLOCKS + BCAST_BLOCKS)

// Per-(b,f) binary mask, computed once by K1. 16 KB -> L2/L1 resident.
__device__ __align__(16) float g_mask[B * F];

// ---------------------------------------------------------------------------
// K1: binary[b,f].  grid=16, block=256. O(F) LDS count loop per thread.
// kept(f) <=> #{j : x2[j] > x2[f]} < KKEEP   (tie-correct vs top_k kth value)
// binary  = kept && (x2 > 0)                 (probs > 0.5 <=> wta > 0)
// ---------------------------------------------------------------------------
__global__ void mask_kernel(const float* __restrict__ w_mask,
                            const float* __restrict__ noise) {
    __shared__ float s[F];
    const int b = blockIdx.x;
    const int f = threadIdx.x;

    const float w  = w_mask[f];
    const float sg = 1.0f / (1.0f + __expf(-w));
    const float x2 = sg + 0.05f * noise[b * F + f];
    s[f] = x2;
    __syncthreads();

    int gt = 0;
#pragma unroll 16
    for (int j = 0; j < F; ++j)
        gt += (s[j] > x2) ? 1 : 0;
    g_mask[b * F + f] = (gt < KKEEP && x2 > 0.0f) ? 1.0f : 0.0f;
}

// ---------------------------------------------------------------------------
// K2: merged streamer, zero barriers (R2 geometry) + read-skip.
//   blocks [0, 8192):    masked_x. Block covers 1024 f4 inside ONE (b,f) row
//                        (rows are 2048 f4) -> mask value uniform per block.
//                        One broadcast LDG of m, then copy*m or store zeros.
//   blocks [8192, 16384): binary_mask (write-only broadcast of mask row).
// ---------------------------------------------------------------------------
__global__ void stream_kernel(const float4* __restrict__ x,
                              float4* __restrict__ out) {
    const int tid = threadIdx.x;                      // 256 threads

    if (blockIdx.x < MASKED_BLOCKS) {
        const int baseV = blockIdx.x * BLK_F4;        // first f4 index
        const int row   = baseV >> 11;                // (b*F + f), uniform
        const float m   = __ldg(&g_mask[row]);        // L1 broadcast

        if (m != 0.0f) {
            float4 xv[4];
#pragma unroll
            for (int k = 0; k < 4; ++k)               // front-batched (MLP=4)
                xv[k] = __ldcs(&x[baseV + k * 256 + tid]);
#pragma unroll
            for (int k = 0; k < 4; ++k)
                __stcs(&out[baseV + k * 256 + tid], xv[k]);
        } else {
            const float4 z = make_float4(0.f, 0.f, 0.f, 0.f);
#pragma unroll
            for (int k = 0; k < 4; ++k)               // row dropped: no reads
                __stcs(&out[baseV + k * 256 + tid], z);
        }
    } else {
        const int w0 = (blockIdx.x - MASKED_BLOCKS) * BLK_F4;
        const int b  = w0 >> 19;                      // T*F/4 f4 per batch
        const int baseV = N4_MASKED + w0;
        // f4 lane = (w0 + k*256 + tid) & 63 = tid & 63 (w0, 256 ≡ 0 mod 64)
        const float4 m4 =
            __ldg(&((const float4*)g_mask)[(b << 6) + (tid & 63)]);
#pragma unroll
        for (int k = 0; k < 4; ++k)
            __stcs(&out[baseV + k * 256 + tid], m4);
    }
}

extern "C" void kernel_launch(void* const* d_in, const int* in_sizes, int n_in,
                              void* d_out, int out_size) {
    const float* x      = (const float*)d_in[0];   // (16,1,256,8192) f32
    const float* w_mask = (const float*)d_in[1];   // (1,1,1,256)     f32
    const float* noise  = (const float*)d_in[2];   // (16,1,1,256)    f32
    float* out = (float*)d_out;

    mask_kernel<<<B, F>>>(w_mask, noise);

    const bool has_bcast = ((long long)out_size >= 2LL * N1);
    const int blocks = has_bcast ? GRID_TOTAL : MASKED_BLOCKS;
    stream_kernel<<<blocks, 256>>>((const float4*)x, (float4*)out);
}